// round 3
// baseline (speedup 1.0000x reference)
#include <cuda_runtime.h>
#include <math.h>

// Skipgram negative-sampling loss — single fused kernel.
// Inputs (metadata order):
//   d_in[0] center_id       int32 [B]
//   d_in[1] pos_context_id  int32 [B]
//   d_in[2] neg_context_ids int32 [B, K]
//   d_in[3] W_in            f32   [VOCAB, DIM]
//   d_in[4] W_out           f32   [VOCAB, DIM]
// Output: scalar f32 = -(sum log_sigmoid(pos_score) + sum log_sigmoid(-neg_score))

#define BATCH 16384
#define KNEG  10
#define DIMV4 32          // 128 floats = 32 float4 per row
#define NBLK  2048        // BATCH / 8 warps per block

__device__ float g_partial[NBLK];
__device__ unsigned int g_count = 0;   // reset by last block each call (graph-replay safe)

__device__ __forceinline__ float log_sigmoid(float x) {
    // stable: min(x,0) - log1p(exp(-|x|))
    return fminf(x, 0.0f) - log1pf(__expf(-fabsf(x)));
}

__global__ __launch_bounds__(256) void skipgram_fused(
    const int* __restrict__ center_id,
    const int* __restrict__ pos_id,
    const int* __restrict__ neg_ids,
    const float4* __restrict__ Win,
    const float4* __restrict__ Wout,
    float* __restrict__ out)
{
    const int lane = threadIdx.x & 31;
    const int warp_in_blk = threadIdx.x >> 5;
    const int b = blockIdx.x * 8 + warp_in_blk;   // one warp per batch element

    // Gather indices (lane-parallel for negatives, broadcast via shfl).
    const int cid = center_id[b];
    const int pid = pos_id[b];
    int my_nid = 0;
    if (lane < KNEG) my_nid = neg_ids[b * KNEG + lane];

    // Each lane loads one float4 of each 512B row (fully coalesced).
    const float4 c = Win [(size_t)cid * DIMV4 + lane];
    const float4 p = Wout[(size_t)pid * DIMV4 + lane];

    float4 nsum = make_float4(0.f, 0.f, 0.f, 0.f);
#pragma unroll
    for (int k = 0; k < KNEG; ++k) {
        const int id = __shfl_sync(0xffffffffu, my_nid, k);
        const float4 v = Wout[(size_t)id * DIMV4 + lane];
        nsum.x += v.x; nsum.y += v.y; nsum.z += v.z; nsum.w += v.w;
    }

    float pd = c.x * p.x + c.y * p.y + c.z * p.z + c.w * p.w;
    float nd = c.x * nsum.x + c.y * nsum.y + c.z * nsum.z + c.w * nsum.w;

#pragma unroll
    for (int o = 16; o > 0; o >>= 1) {
        pd += __shfl_xor_sync(0xffffffffu, pd, o);
        nd += __shfl_xor_sync(0xffffffffu, nd, o);
    }

    __shared__ float s[8];
    __shared__ bool is_last;
    if (lane == 0)
        s[warp_in_blk] = log_sigmoid(pd) + log_sigmoid(-nd);
    __syncthreads();

    if (threadIdx.x == 0) {
        float t = 0.f;
#pragma unroll
        for (int i = 0; i < 8; ++i) t += s[i];
        g_partial[blockIdx.x] = t;
        __threadfence();
        unsigned int old = atomicAdd(&g_count, 1u);
        is_last = (old == NBLK - 1);
    }
    __syncthreads();

    if (is_last) {
        // Last block: deterministic fixed-order reduction of all partials.
        float t = 0.f;
#pragma unroll
        for (int i = 0; i < NBLK / 256; ++i)
            t += g_partial[threadIdx.x + i * 256];   // 8 loads per thread, fixed order

#pragma unroll
        for (int o = 16; o > 0; o >>= 1)
            t += __shfl_xor_sync(0xffffffffu, t, o);

        __shared__ float s2[8];
        if (lane == 0) s2[warp_in_blk] = t;
        __syncthreads();

        if (threadIdx.x == 0) {
            float tot = 0.f;
#pragma unroll
            for (int i = 0; i < 8; ++i) tot += s2[i];
            out[0] = -tot;
            g_count = 0;   // reset for next graph replay
        }
    }
}

extern "C" void kernel_launch(void* const* d_in, const int* in_sizes, int n_in,
                              void* d_out, int out_size)
{
    const int*    center_id = (const int*)   d_in[0];
    const int*    pos_id    = (const int*)   d_in[1];
    const int*    neg_ids   = (const int*)   d_in[2];
    const float4* Win       = (const float4*)d_in[3];
    const float4* Wout      = (const float4*)d_in[4];
    float* out = (float*)d_out;

    skipgram_fused<<<NBLK, 256>>>(center_id, pos_id, neg_ids, Win, Wout, out);
}